// round 1
// baseline (speedup 1.0000x reference)
#include <cuda_runtime.h>
#include <mma.h>
#include <math.h>

using namespace nvcuda;

#define BB 2
#define SS 2048
#define EE 1024
#define HH 16
#define DD 64
#define MM (BB * SS)   // 4096

// Scratch (no cudaMalloc allowed): Q,K,V stored [B,H,S,D]; O stored [M,E]
__device__ float g_Q[MM * EE];
__device__ float g_K[MM * EE];
__device__ float g_V[MM * EE];
__device__ float g_O[MM * EE];

// ---------------------------------------------------------------------------
// GEMM: Y = X @ W^T + b   (X [M,E] row-major, W [N,E] row-major -> NT gemm)
// MODE 0: z in {0,1,2} selects (Wq,bq)->g_Q etc., output scattered to [B,H,S,D]
// MODE 1: X = g_O, W0/b0 = Wo/bo, output plain [M,E] to Yout
// ---------------------------------------------------------------------------
template <int MODE>
__global__ void __launch_bounds__(128)
gemm_nt_kernel(const float* __restrict__ Xin,
               const float* __restrict__ W0, const float* __restrict__ b0,
               const float* __restrict__ W1, const float* __restrict__ b1,
               const float* __restrict__ W2, const float* __restrict__ b2,
               float* __restrict__ Yout)
{
    constexpr int BK  = 32;
    constexpr int LDA = BK + 4;  // 36, pad to dodge bank conflicts

    __shared__ float sA[64][LDA];
    __shared__ float sB[64][LDA];
    __shared__ float sC[64][64];

    const float* X;
    const float* W;
    const float* bias;
    float* Y;

    if (MODE == 0) {
        int z = blockIdx.z;
        X    = Xin;
        W    = (z == 0) ? W0 : (z == 1) ? W1 : W2;
        bias = (z == 0) ? b0 : (z == 1) ? b1 : b2;
        Y    = (z == 0) ? g_Q : (z == 1) ? g_K : g_V;
    } else {
        X = g_O; W = W0; bias = b0; Y = Yout;
    }

    const int tid  = threadIdx.x;
    const int warp = tid >> 5;
    const int m0   = blockIdx.x * 64;
    const int n0   = blockIdx.y * 64;
    const int wm   = (warp >> 1) * 32;  // warp row offset within tile
    const int wn   = (warp & 1) * 32;   // warp col offset within tile

    wmma::fragment<wmma::accumulator, 16, 16, 8, float> acc[2][2];
#pragma unroll
    for (int i = 0; i < 2; i++)
#pragma unroll
        for (int j = 0; j < 2; j++) wmma::fill_fragment(acc[i][j], 0.0f);

    for (int k0 = 0; k0 < EE; k0 += BK) {
        __syncthreads();
        // Load 64x32 A tile and 64x32 B tile (512 float4 each, 128 threads)
#pragma unroll
        for (int i = 0; i < 4; i++) {
            int idx = tid + i * 128;
            int r = idx >> 3;
            int c = (idx & 7) * 4;
            *(float4*)&sA[r][c] = *(const float4*)(X + (size_t)(m0 + r) * EE + k0 + c);
            *(float4*)&sB[r][c] = *(const float4*)(W + (size_t)(n0 + r) * EE + k0 + c);
        }
        __syncthreads();

#pragma unroll
        for (int kk = 0; kk < BK; kk += 8) {
            wmma::fragment<wmma::matrix_a, 16, 16, 8, wmma::precision::tf32, wmma::row_major> af[2];
            wmma::fragment<wmma::matrix_b, 16, 16, 8, wmma::precision::tf32, wmma::col_major> bf[2];
#pragma unroll
            for (int i = 0; i < 2; i++) {
                wmma::load_matrix_sync(af[i], &sA[wm + i * 16][kk], LDA);
#pragma unroll
                for (int t = 0; t < af[i].num_elements; t++)
                    af[i].x[t] = wmma::__float_to_tf32(af[i].x[t]);
                wmma::load_matrix_sync(bf[i], &sB[wn + i * 16][kk], LDA);
#pragma unroll
                for (int t = 0; t < bf[i].num_elements; t++)
                    bf[i].x[t] = wmma::__float_to_tf32(bf[i].x[t]);
            }
#pragma unroll
            for (int i = 0; i < 2; i++)
#pragma unroll
                for (int j = 0; j < 2; j++)
                    wmma::mma_sync(acc[i][j], af[i], bf[j], acc[i][j]);
        }
    }

    __syncthreads();
#pragma unroll
    for (int i = 0; i < 2; i++)
#pragma unroll
        for (int j = 0; j < 2; j++)
            wmma::store_matrix_sync(&sC[wm + i * 16][wn + j * 16], acc[i][j], 64,
                                    wmma::mem_row_major);
    __syncthreads();

    for (int idx = tid; idx < 64 * 64; idx += 128) {
        int r = idx >> 6, c = idx & 63;
        int m = m0 + r, f = n0 + c;
        float v = sC[r][c] + bias[f];
        if (MODE == 0) {
            int b = m / SS, s = m % SS;
            int h = f / DD, d = f % DD;
            Y[(((size_t)(b * HH + h)) * SS + s) * DD + d] = v;
        } else {
            Y[(size_t)m * EE + f] = v;
        }
    }
}

// ---------------------------------------------------------------------------
// Flash attention: per (b,h), 64-query tiles streaming over 64-key tiles.
// tf32 wmma for QK^T and PV; fp32 online softmax. Each warp owns score rows
// [16w, 16w+16) end-to-end -> only warp-local sync after the tile loads.
// ---------------------------------------------------------------------------
__global__ void __launch_bounds__(128) attn_kernel()
{
    extern __shared__ float sh[];
    float* Qs  = sh;           // 64 x 64
    float* Ks  = sh + 4096;    // 64 x 64
    float* Vs  = sh + 8192;    // 64 x 64
    float* Sst = sh + 12288;   // 64 x 64 (scores, then P, then PV)

    const int tid  = threadIdx.x;
    const int warp = tid >> 5;
    const int bh   = blockIdx.y;
    const int q0   = blockIdx.x * 64;

    const float* Qg = g_Q + (size_t)bh * SS * DD;
    const float* Kg = g_K + (size_t)bh * SS * DD;
    const float* Vg = g_V + (size_t)bh * SS * DD;

    // Load Q tile (64x64 = 1024 float4)
#pragma unroll
    for (int i = 0; i < 8; i++) {
        int idx = tid + i * 128;
        int r = idx >> 4, c = (idx & 15) * 4;
        *(float4*)&Qs[r * 64 + c] = *(const float4*)(Qg + (size_t)(q0 + r) * 64 + c);
    }

    const int row  = tid >> 1;          // owned score row
    const int colh = (tid & 1) * 32;    // half-row of columns
    float o[32];
#pragma unroll
    for (int i = 0; i < 32; i++) o[i] = 0.0f;
    float m_prev = -INFINITY, l = 0.0f;
    const float sm_scale = rsqrtf((float)DD);

    for (int j = 0; j < SS / 64; j++) {
        __syncthreads();  // all warps done with previous K/V/S tiles
#pragma unroll
        for (int i = 0; i < 8; i++) {
            int idx = tid + i * 128;
            int r = idx >> 4, c = (idx & 15) * 4;
            *(float4*)&Ks[r * 64 + c] = *(const float4*)(Kg + (size_t)(j * 64 + r) * 64 + c);
            *(float4*)&Vs[r * 64 + c] = *(const float4*)(Vg + (size_t)(j * 64 + r) * 64 + c);
        }
        __syncthreads();

        // ---- S = Q K^T : warp computes rows [16w,16w+16) x 64 cols ----
        {
            wmma::fragment<wmma::accumulator, 16, 16, 8, float> acc[4];
#pragma unroll
            for (int n = 0; n < 4; n++) wmma::fill_fragment(acc[n], 0.0f);
#pragma unroll
            for (int kk = 0; kk < 64; kk += 8) {
                wmma::fragment<wmma::matrix_a, 16, 16, 8, wmma::precision::tf32, wmma::row_major> af;
                wmma::load_matrix_sync(af, &Qs[(warp * 16) * 64 + kk], 64);
#pragma unroll
                for (int t = 0; t < af.num_elements; t++) af.x[t] = wmma::__float_to_tf32(af.x[t]);
#pragma unroll
                for (int n = 0; n < 4; n++) {
                    wmma::fragment<wmma::matrix_b, 16, 16, 8, wmma::precision::tf32, wmma::col_major> bf;
                    wmma::load_matrix_sync(bf, &Ks[(n * 16) * 64 + kk], 64);
#pragma unroll
                    for (int t = 0; t < bf.num_elements; t++) bf.x[t] = wmma::__float_to_tf32(bf.x[t]);
                    wmma::mma_sync(acc[n], af, bf, acc[n]);
                }
            }
#pragma unroll
            for (int n = 0; n < 4; n++)
                wmma::store_matrix_sync(&Sst[(warp * 16) * 64 + n * 16], acc[n], 64,
                                        wmma::mem_row_major);
        }
        __syncwarp();  // warp reads only the rows it just stored

        // ---- online softmax on the owned half-row ----
        float* srow = Sst + row * 64 + colh;
        float mx = -INFINITY;
#pragma unroll
        for (int i = 0; i < 32; i++) mx = fmaxf(mx, srow[i]);
        mx = fmaxf(mx, __shfl_xor_sync(0xffffffffu, mx, 1));
        float m_new = fmaxf(m_prev, mx * sm_scale);
        float sum = 0.0f;
#pragma unroll
        for (int i = 0; i < 32; i++) {
            float p = __expf(srow[i] * sm_scale - m_new);
            srow[i] = p;
            sum += p;
        }
        sum += __shfl_xor_sync(0xffffffffu, sum, 1);
        float corr = __expf(m_prev - m_new);
        l = l * corr + sum;
#pragma unroll
        for (int i = 0; i < 32; i++) o[i] *= corr;
        m_prev = m_new;
        __syncwarp();

        // ---- PV: warp rows [16w,16w+16) of P times V[64,64] ----
        {
            wmma::fragment<wmma::accumulator, 16, 16, 8, float> acc[4];
#pragma unroll
            for (int n = 0; n < 4; n++) wmma::fill_fragment(acc[n], 0.0f);
#pragma unroll
            for (int kk = 0; kk < 64; kk += 8) {
                wmma::fragment<wmma::matrix_a, 16, 16, 8, wmma::precision::tf32, wmma::row_major> af;
                wmma::load_matrix_sync(af, &Sst[(warp * 16) * 64 + kk], 64);
#pragma unroll
                for (int t = 0; t < af.num_elements; t++) af.x[t] = wmma::__float_to_tf32(af.x[t]);
#pragma unroll
                for (int n = 0; n < 4; n++) {
                    wmma::fragment<wmma::matrix_b, 16, 16, 8, wmma::precision::tf32, wmma::row_major> bf;
                    wmma::load_matrix_sync(bf, &Vs[kk * 64 + n * 16], 64);
#pragma unroll
                    for (int t = 0; t < bf.num_elements; t++) bf.x[t] = wmma::__float_to_tf32(bf.x[t]);
                    wmma::mma_sync(acc[n], af, bf, acc[n]);
                }
            }
            // overwrite P with PV (warp-local rows; frag reads already done)
#pragma unroll
            for (int n = 0; n < 4; n++)
                wmma::store_matrix_sync(&Sst[(warp * 16) * 64 + n * 16], acc[n], 64,
                                        wmma::mem_row_major);
        }
        __syncwarp();
#pragma unroll
        for (int i = 0; i < 32; i++) o[i] += srow[i];
    }

    // normalize and write to g_O[m, h*D + d]
    float inv_l = 1.0f / l;
    int b = bh / HH, h = bh % HH;
    size_t m = (size_t)b * SS + q0 + row;
    float* dst = g_O + m * EE + h * DD + colh;
#pragma unroll
    for (int i = 0; i < 32; i++) dst[i] = o[i] * inv_l;
}

// ---------------------------------------------------------------------------
extern "C" void kernel_launch(void* const* d_in, const int* in_sizes, int n_in,
                              void* d_out, int out_size)
{
    const float* x  = (const float*)d_in[0];
    const float* Wq = (const float*)d_in[1];
    const float* bq = (const float*)d_in[2];
    const float* Wk = (const float*)d_in[3];
    const float* bk = (const float*)d_in[4];
    const float* Wv = (const float*)d_in[5];
    const float* bv = (const float*)d_in[6];
    const float* Wo = (const float*)d_in[7];
    const float* bo = (const float*)d_in[8];
    float* out = (float*)d_out;

    (void)in_sizes; (void)n_in; (void)out_size;

    cudaFuncSetAttribute(attn_kernel, cudaFuncAttributeMaxDynamicSharedMemorySize, 65536);

    dim3 gq(MM / 64, EE / 64, 3);
    gemm_nt_kernel<0><<<gq, 128>>>(x, Wq, bq, Wk, bk, Wv, bv, nullptr);

    attn_kernel<<<dim3(SS / 64, BB * HH), 128, 65536>>>();

    dim3 go(MM / 64, EE / 64, 1);
    gemm_nt_kernel<1><<<go, 128>>>(nullptr, Wo, bo, nullptr, nullptr, nullptr, nullptr, out);
}

// round 2
// speedup vs baseline: 2.3671x; 2.3671x over previous
#include <cuda_runtime.h>
#include <mma.h>
#include <math.h>

using namespace nvcuda;

#define BB 2
#define SS 2048
#define EE 1024
#define HH 16
#define DD 64
#define MM (BB * SS)   // 4096

// Scratch (no cudaMalloc allowed): Q,K,V stored [B,H,S,D]; O stored [M,E]
__device__ float g_Q[MM * EE];
__device__ float g_K[MM * EE];
__device__ float g_V[MM * EE];
__device__ float g_O[MM * EE];

// ---------------------------------------------------------------------------
// helpers
// ---------------------------------------------------------------------------
__device__ __forceinline__ unsigned f2tf(float f) {
    unsigned u;
    asm("cvt.rna.tf32.f32 %0, %1;" : "=r"(u) : "f"(f));
    return u;
}
__device__ __forceinline__ float ex2f(float x) {
    float y;
    asm("ex2.approx.f32 %0, %1;" : "=f"(y) : "f"(x));
    return y;
}
__device__ __forceinline__ void mma8(float* c, const unsigned* a, unsigned b0, unsigned b1) {
    asm volatile(
        "mma.sync.aligned.m16n8k8.row.col.f32.tf32.tf32.f32 "
        "{%0,%1,%2,%3}, {%4,%5,%6,%7}, {%8,%9}, {%0,%1,%2,%3};"
        : "+f"(c[0]), "+f"(c[1]), "+f"(c[2]), "+f"(c[3])
        : "r"(a[0]), "r"(a[1]), "r"(a[2]), "r"(a[3]), "r"(b0), "r"(b1));
}
__device__ __forceinline__ void cp16(float* smem, const float* gmem) {
    unsigned s = (unsigned)__cvta_generic_to_shared(smem);
    asm volatile("cp.async.cg.shared.global [%0], [%1], 16;" :: "r"(s), "l"(gmem));
}

// ---------------------------------------------------------------------------
// GEMM: Y = X @ W^T + b   (X [M,E] row-major, W [N,E] row-major -> NT gemm)
// MODE 0: z in {0,1,2} selects (Wq,bq)->g_Q etc., output scattered to [B,H,S,D],
//         values pre-rounded to tf32 so attention can consume raw bits.
// MODE 1: X = g_O, W0/b0 = Wo/bo, output plain [M,E] to Yout
// ---------------------------------------------------------------------------
template <int MODE>
__global__ void __launch_bounds__(128)
gemm_nt_kernel(const float* __restrict__ Xin,
               const float* __restrict__ W0, const float* __restrict__ b0,
               const float* __restrict__ W1, const float* __restrict__ b1,
               const float* __restrict__ W2, const float* __restrict__ b2,
               float* __restrict__ Yout)
{
    constexpr int BK  = 32;
    constexpr int LDA = BK + 4;  // 36, pad to dodge bank conflicts

    __shared__ float sA[64][LDA];
    __shared__ float sB[64][LDA];
    __shared__ float sC[64][64];

    const float* X;
    const float* W;
    const float* bias;
    float* Y;

    if (MODE == 0) {
        int z = blockIdx.z;
        X    = Xin;
        W    = (z == 0) ? W0 : (z == 1) ? W1 : W2;
        bias = (z == 0) ? b0 : (z == 1) ? b1 : b2;
        Y    = (z == 0) ? g_Q : (z == 1) ? g_K : g_V;
    } else {
        X = g_O; W = W0; bias = b0; Y = Yout;
    }

    const int tid  = threadIdx.x;
    const int warp = tid >> 5;
    const int m0   = blockIdx.x * 64;
    const int n0   = blockIdx.y * 64;
    const int wm   = (warp >> 1) * 32;
    const int wn   = (warp & 1) * 32;

    wmma::fragment<wmma::accumulator, 16, 16, 8, float> acc[2][2];
#pragma unroll
    for (int i = 0; i < 2; i++)
#pragma unroll
        for (int j = 0; j < 2; j++) wmma::fill_fragment(acc[i][j], 0.0f);

    for (int k0 = 0; k0 < EE; k0 += BK) {
        __syncthreads();
#pragma unroll
        for (int i = 0; i < 4; i++) {
            int idx = tid + i * 128;
            int r = idx >> 3;
            int c = (idx & 7) * 4;
            *(float4*)&sA[r][c] = *(const float4*)(X + (size_t)(m0 + r) * EE + k0 + c);
            *(float4*)&sB[r][c] = *(const float4*)(W + (size_t)(n0 + r) * EE + k0 + c);
        }
        __syncthreads();

#pragma unroll
        for (int kk = 0; kk < BK; kk += 8) {
            wmma::fragment<wmma::matrix_a, 16, 16, 8, wmma::precision::tf32, wmma::row_major> af[2];
            wmma::fragment<wmma::matrix_b, 16, 16, 8, wmma::precision::tf32, wmma::col_major> bf[2];
#pragma unroll
            for (int i = 0; i < 2; i++) {
                wmma::load_matrix_sync(af[i], &sA[wm + i * 16][kk], LDA);
#pragma unroll
                for (int t = 0; t < af[i].num_elements; t++)
                    af[i].x[t] = wmma::__float_to_tf32(af[i].x[t]);
                wmma::load_matrix_sync(bf[i], &sB[wn + i * 16][kk], LDA);
#pragma unroll
                for (int t = 0; t < bf[i].num_elements; t++)
                    bf[i].x[t] = wmma::__float_to_tf32(bf[i].x[t]);
            }
#pragma unroll
            for (int i = 0; i < 2; i++)
#pragma unroll
                for (int j = 0; j < 2; j++)
                    wmma::mma_sync(acc[i][j], af[i], bf[j], acc[i][j]);
        }
    }

    __syncthreads();
#pragma unroll
    for (int i = 0; i < 2; i++)
#pragma unroll
        for (int j = 0; j < 2; j++)
            wmma::store_matrix_sync(&sC[wm + i * 16][wn + j * 16], acc[i][j], 64,
                                    wmma::mem_row_major);
    __syncthreads();

    for (int idx = tid; idx < 64 * 64; idx += 128) {
        int r = idx >> 6, c = idx & 63;
        int m = m0 + r, f = n0 + c;
        float v = sC[r][c] + bias[f];
        if (MODE == 0) {
            int b = m / SS, s = m % SS;
            int h = f / DD, d = f % DD;
            // pre-round to tf32: attention consumes raw bits, no per-iter cvt
            g_unused:;
            Y[(((size_t)(b * HH + h)) * SS + s) * DD + d] = __uint_as_float(f2tf(v));
        } else {
            Y[(size_t)m * EE + f] = v;
        }
    }
}

// ---------------------------------------------------------------------------
// Flash attention, FA2-style register-resident, mma.sync m16n8k8 tf32.
// Block: 128 query rows (8 warps x 16 rows), KV tiles of 64 keys,
// cp.async double-buffered K/V. Softmax entirely in registers.
// ---------------------------------------------------------------------------
#define LDS_ 68
#define TILE_F (64 * LDS_)      // floats per K or V tile
#define QSTAGE_F (128 * LDS_)   // Q staging

__global__ void __launch_bounds__(256, 1) attn_kernel()
{
    extern __shared__ float sh[];
    float* Qs = sh;
    float* Kbuf0 = sh + QSTAGE_F;
    float* Vbuf0 = Kbuf0 + TILE_F;
    float* Kbuf1 = Vbuf0 + TILE_F;
    float* Vbuf1 = Kbuf1 + TILE_F;

    const int tid  = threadIdx.x;
    const int warp = tid >> 5;
    const int lane = tid & 31;
    const int g    = lane >> 2;   // group (row within 16-row tile)
    const int q    = lane & 3;    // quad pos
    const int bh   = blockIdx.y;
    const int q0   = blockIdx.x * 128;

    const float* Qg = g_Q + (size_t)bh * SS * DD;
    const float* Kg = g_K + (size_t)bh * SS * DD;
    const float* Vg = g_V + (size_t)bh * SS * DD;

    // prefetch KV tiles 0 and 1
#pragma unroll
    for (int t = 0; t < 2; t++) {
        float* Kd = t ? Kbuf1 : Kbuf0;
        float* Vd = t ? Vbuf1 : Vbuf0;
#pragma unroll
        for (int i = 0; i < 4; i++) {
            int idx = tid + i * 256;
            int r = idx >> 4, c = (idx & 15) * 4;
            cp16(Kd + r * LDS_ + c, Kg + (size_t)(t * 64 + r) * 64 + c);
            cp16(Vd + r * LDS_ + c, Vg + (size_t)(t * 64 + r) * 64 + c);
        }
        asm volatile("cp.async.commit_group;");
    }

    // stage Q (coalesced), then load Q fragments with sm_scale*log2e folded in
#pragma unroll
    for (int i = 0; i < 8; i++) {
        int idx = tid + i * 256;
        int r = idx >> 4, c = (idx & 15) * 4;
        *(float4*)(Qs + r * LDS_ + c) = *(const float4*)(Qg + (size_t)(q0 + r) * 64 + c);
    }
    __syncthreads();

    const float qscale = 0.125f * 1.44269504088896340736f;  // D^-0.5 * log2(e)
    const int rbase = warp * 16;
    unsigned qf[8][4];
#pragma unroll
    for (int ks = 0; ks < 8; ks++) {
        qf[ks][0] = f2tf(Qs[(rbase + g)     * LDS_ + 8 * ks + q]     * qscale);
        qf[ks][1] = f2tf(Qs[(rbase + g + 8) * LDS_ + 8 * ks + q]     * qscale);
        qf[ks][2] = f2tf(Qs[(rbase + g)     * LDS_ + 8 * ks + q + 4] * qscale);
        qf[ks][3] = f2tf(Qs[(rbase + g + 8) * LDS_ + 8 * ks + q + 4] * qscale);
    }

    float o[8][4];
#pragma unroll
    for (int i = 0; i < 8; i++)
#pragma unroll
        for (int k = 0; k < 4; k++) o[i][k] = 0.0f;
    float m0 = -INFINITY, m1 = -INFINITY, l0 = 0.0f, l1 = 0.0f;

    const int src1 = (lane & ~3) | (q >> 1);
    const int src2 = src1 + 2;
    const bool odd = q & 1;

    for (int j = 0; j < SS / 64; j++) {
        asm volatile("cp.async.wait_group 1;");
        __syncthreads();
        const float* K = (j & 1) ? Kbuf1 : Kbuf0;
        const float* V = (j & 1) ? Vbuf1 : Vbuf0;

        // ---- S = (Q*scale) K^T in exp2 domain: 16 x 64 per warp ----
        float s[8][4];
#pragma unroll
        for (int nt = 0; nt < 8; nt++) {
            s[nt][0] = s[nt][1] = s[nt][2] = s[nt][3] = 0.0f;
#pragma unroll
            for (int ks = 0; ks < 8; ks++) {
                unsigned b0 = __float_as_uint(K[(8 * nt + g) * LDS_ + 8 * ks + q]);
                unsigned b1 = __float_as_uint(K[(8 * nt + g) * LDS_ + 8 * ks + q + 4]);
                mma8(s[nt], qf[ks], b0, b1);
            }
        }

        // ---- online softmax (rows g and g+8), quad reductions ----
        float mx0 = -INFINITY, mx1 = -INFINITY;
#pragma unroll
        for (int nt = 0; nt < 8; nt++) {
            mx0 = fmaxf(mx0, fmaxf(s[nt][0], s[nt][1]));
            mx1 = fmaxf(mx1, fmaxf(s[nt][2], s[nt][3]));
        }
        mx0 = fmaxf(mx0, __shfl_xor_sync(0xffffffffu, mx0, 1));
        mx0 = fmaxf(mx0, __shfl_xor_sync(0xffffffffu, mx0, 2));
        mx1 = fmaxf(mx1, __shfl_xor_sync(0xffffffffu, mx1, 1));
        mx1 = fmaxf(mx1, __shfl_xor_sync(0xffffffffu, mx1, 2));
        float mn0 = fmaxf(m0, mx0), mn1 = fmaxf(m1, mx1);
        float cr0 = ex2f(m0 - mn0), cr1 = ex2f(m1 - mn1);
        float rs0 = 0.0f, rs1 = 0.0f;
#pragma unroll
        for (int nt = 0; nt < 8; nt++) {
            s[nt][0] = ex2f(s[nt][0] - mn0);
            s[nt][1] = ex2f(s[nt][1] - mn0);
            s[nt][2] = ex2f(s[nt][2] - mn1);
            s[nt][3] = ex2f(s[nt][3] - mn1);
            rs0 += s[nt][0] + s[nt][1];
            rs1 += s[nt][2] + s[nt][3];
        }
        rs0 += __shfl_xor_sync(0xffffffffu, rs0, 1);
        rs0 += __shfl_xor_sync(0xffffffffu, rs0, 2);
        rs1 += __shfl_xor_sync(0xffffffffu, rs1, 1);
        rs1 += __shfl_xor_sync(0xffffffffu, rs1, 2);
        l0 = l0 * cr0 + rs0;
        l1 = l1 * cr1 + rs1;
#pragma unroll
        for (int nt = 0; nt < 8; nt++) {
            o[nt][0] *= cr0; o[nt][1] *= cr0;
            o[nt][2] *= cr1; o[nt][3] *= cr1;
        }
        m0 = mn0; m1 = mn1;

        // ---- permute P (C layout) -> A fragments via quad shuffles ----
        unsigned pf[8][4];
#pragma unroll
        for (int nt = 0; nt < 8; nt++) {
            float v00 = __shfl_sync(0xffffffffu, s[nt][0], src1);
            float v01 = __shfl_sync(0xffffffffu, s[nt][1], src1);
            float v10 = __shfl_sync(0xffffffffu, s[nt][2], src1);
            float v11 = __shfl_sync(0xffffffffu, s[nt][3], src1);
            float w00 = __shfl_sync(0xffffffffu, s[nt][0], src2);
            float w01 = __shfl_sync(0xffffffffu, s[nt][1], src2);
            float w10 = __shfl_sync(0xffffffffu, s[nt][2], src2);
            float w11 = __shfl_sync(0xffffffffu, s[nt][3], src2);
            pf[nt][0] = f2tf(odd ? v01 : v00);
            pf[nt][1] = f2tf(odd ? v11 : v10);
            pf[nt][2] = f2tf(odd ? w01 : w00);
            pf[nt][3] = f2tf(odd ? w11 : w10);
        }

        // ---- O += P V ----
#pragma unroll
        for (int nt2 = 0; nt2 < 8; nt2++) {
#pragma unroll
            for (int t = 0; t < 8; t++) {
                unsigned b0 = __float_as_uint(V[(8 * t + q)     * LDS_ + 8 * nt2 + g]);
                unsigned b1 = __float_as_uint(V[(8 * t + q + 4) * LDS_ + 8 * nt2 + g]);
                mma8(o[nt2], pf[t], b0, b1);
            }
        }

        __syncthreads();
        // prefetch tile j+2 into the buffer tile j used
        if (j + 2 < SS / 64) {
            float* Kd = (j & 1) ? Kbuf1 : Kbuf0;
            float* Vd = (j & 1) ? Vbuf1 : Vbuf0;
#pragma unroll
            for (int i = 0; i < 4; i++) {
                int idx = tid + i * 256;
                int r = idx >> 4, c = (idx & 15) * 4;
                cp16(Kd + r * LDS_ + c, Kg + (size_t)((j + 2) * 64 + r) * 64 + c);
                cp16(Vd + r * LDS_ + c, Vg + (size_t)((j + 2) * 64 + r) * 64 + c);
            }
        }
        asm volatile("cp.async.commit_group;");
    }

    // ---- epilogue: normalize, write g_O[m, h*D + d] ----
    float inv0 = 1.0f / l0, inv1 = 1.0f / l1;
    int b = bh / HH, h = bh % HH;
    size_t row0 = (size_t)b * SS + q0 + rbase + g;
    float* d0 = g_O + row0 * EE + h * DD;
    float* d1 = d0 + 8 * EE;
#pragma unroll
    for (int nt2 = 0; nt2 < 8; nt2++) {
        float2 u; u.x = o[nt2][0] * inv0; u.y = o[nt2][1] * inv0;
        *(float2*)(d0 + 8 * nt2 + 2 * q) = u;
        float2 w; w.x = o[nt2][2] * inv1; w.y = o[nt2][3] * inv1;
        *(float2*)(d1 + 8 * nt2 + 2 * q) = w;
    }
}

// ---------------------------------------------------------------------------
extern "C" void kernel_launch(void* const* d_in, const int* in_sizes, int n_in,
                              void* d_out, int out_size)
{
    const float* x  = (const float*)d_in[0];
    const float* Wq = (const float*)d_in[1];
    const float* bq = (const float*)d_in[2];
    const float* Wk = (const float*)d_in[3];
    const float* bk = (const float*)d_in[4];
    const float* Wv = (const float*)d_in[5];
    const float* bv = (const float*)d_in[6];
    const float* Wo = (const float*)d_in[7];
    const float* bo = (const float*)d_in[8];
    float* out = (float*)d_out;

    (void)in_sizes; (void)n_in; (void)out_size;

    const int attn_smem = (QSTAGE_F + 4 * TILE_F) * sizeof(float);
    cudaFuncSetAttribute(attn_kernel, cudaFuncAttributeMaxDynamicSharedMemorySize, attn_smem);

    dim3 gq(MM / 64, EE / 64, 3);
    gemm_nt_kernel<0><<<gq, 128>>>(x, Wq, bq, Wk, bk, Wv, bv, nullptr);

    attn_kernel<<<dim3(SS / 128, BB * HH), 256, attn_smem>>>();

    dim3 go(MM / 64, EE / 64, 1);
    gemm_nt_kernel<1><<<go, 128>>>(nullptr, Wo, bo, nullptr, nullptr, nullptr, nullptr, out);
}

// round 4
// speedup vs baseline: 3.0146x; 1.2736x over previous
#include <cuda_runtime.h>
#include <math.h>

#define BB 2
#define SS 2048
#define EE 1024
#define HH 16
#define DD 64
#define MM (BB * SS)   // 4096

// Scratch: exactly 64 MiB of __device__ globals (R2-proven footprint).
// g_O triple-duty: rounded X for QKV proj -> attention output for O proj.
__device__ float g_Q[MM * EE];          // [B,H,S,D] tf32-rounded
__device__ float g_K[MM * EE];
__device__ float g_V[MM * EE];
__device__ float g_O[MM * EE];          // [M,E] tf32-rounded (X, then attn O)

// ---------------------------------------------------------------------------
// helpers
// ---------------------------------------------------------------------------
__device__ __forceinline__ unsigned f2tf(float f) {
    unsigned u;
    asm("cvt.rna.tf32.f32 %0, %1;" : "=r"(u) : "f"(f));
    return u;
}
__device__ __forceinline__ float ex2f(float x) {
    float y;
    asm("ex2.approx.f32 %0, %1;" : "=f"(y) : "f"(x));
    return y;
}
__device__ __forceinline__ void mma8(float* c, const unsigned* a, unsigned b0, unsigned b1) {
    asm volatile(
        "mma.sync.aligned.m16n8k8.row.col.f32.tf32.tf32.f32 "
        "{%0,%1,%2,%3}, {%4,%5,%6,%7}, {%8,%9}, {%0,%1,%2,%3};"
        : "+f"(c[0]), "+f"(c[1]), "+f"(c[2]), "+f"(c[3])
        : "r"(a[0]), "r"(a[1]), "r"(a[2]), "r"(a[3]), "r"(b0), "r"(b1));
}
__device__ __forceinline__ void cp16(float* smem, const float* gmem) {
    unsigned s = (unsigned)__cvta_generic_to_shared(smem);
    asm volatile("cp.async.cg.shared.global [%0], [%1], 16;" :: "r"(s), "l"(gmem));
}

// ---------------------------------------------------------------------------
// round x -> tf32, written straight into g_O (symbol referenced in-kernel)
// ---------------------------------------------------------------------------
__global__ void __launch_bounds__(256) round_x_kernel(const float4* __restrict__ src)
{
    int i = blockIdx.x * 256 + threadIdx.x;
    float4 v = src[i];
    v.x = __uint_as_float(f2tf(v.x));
    v.y = __uint_as_float(f2tf(v.y));
    v.z = __uint_as_float(f2tf(v.z));
    v.w = __uint_as_float(f2tf(v.w));
    ((float4*)g_O)[i] = v;
}

// ---------------------------------------------------------------------------
// Tensor-core NT GEMM: C[M,N] = A[M,K] @ W[N,K]^T + bias
// A read from g_O (pre-rounded tf32 bits, no cvt). W raw fp32, inline cvt on
// B-fragment loads. 128x128x32 tiles, 256 threads, cp.async double buffered.
// MODE 0: z selects W/bias; scatter to Q/K/V [B,H,S,D], tf32-rounded.
// MODE 1: plain [M,E] fp32 output to Yout.
// ---------------------------------------------------------------------------
#define GLD 36                       // padded smem row stride (floats)
#define GSTAGE (128 * GLD)           // floats per operand stage

template <int MODE>
__global__ void __launch_bounds__(256)
gemm_tc(const float* __restrict__ W0, const float* __restrict__ b0v,
        const float* __restrict__ W1, const float* __restrict__ b1v,
        const float* __restrict__ W2, const float* __restrict__ b2v,
        float* __restrict__ Yout)
{
    extern __shared__ float sh[];

    const float* Ag = g_O;
    const float* W;
    const float* bias;
    float* Y;
    if (MODE == 0) {
        int z = blockIdx.z;
        W    = (z == 0) ? W0 : (z == 1) ? W1 : W2;
        bias = (z == 0) ? b0v : (z == 1) ? b1v : b2v;
        Y    = (z == 0) ? g_Q : (z == 1) ? g_K : g_V;
    } else {
        W    = W0;
        bias = b0v;
        Y    = Yout;
    }

    const int tid  = threadIdx.x;
    const int warp = tid >> 5;
    const int lane = tid & 31;
    const int g    = lane >> 2;
    const int q    = lane & 3;
    const int m0   = blockIdx.x * 128;
    const int n0   = blockIdx.y * 128;
    const int wm   = (warp >> 1) * 32;   // 4 warp-rows of 32
    const int wn   = (warp & 1) * 64;    // 2 warp-cols of 64

    const int lr = tid >> 1;             // load row 0..127
    const int lc = (tid & 1) * 16;       // load col base 0/16

    float acc[2][8][4];
#pragma unroll
    for (int mt = 0; mt < 2; mt++)
#pragma unroll
        for (int nt = 0; nt < 8; nt++)
#pragma unroll
            for (int t = 0; t < 4; t++) acc[mt][nt][t] = 0.0f;

    // prefetch stages 0,1
#pragma unroll
    for (int st = 0; st < 2; st++) {
        float* As = sh + st * 2 * GSTAGE;
        float* Bs = As + GSTAGE;
        int k0 = st * 32;
#pragma unroll
        for (int i = 0; i < 4; i++) {
            int cc = lc + i * 4;
            cp16(As + lr * GLD + cc, Ag + (size_t)(m0 + lr) * EE + k0 + cc);
            cp16(Bs + lr * GLD + cc, W  + (size_t)(n0 + lr) * EE + k0 + cc);
        }
        asm volatile("cp.async.commit_group;");
    }

    const int NITER = EE / 32;
    for (int it = 0; it < NITER; it++) {
        asm volatile("cp.async.wait_group 1;");
        __syncthreads();
        const float* As = sh + (it & 1) * 2 * GSTAGE;
        const float* Bs = As + GSTAGE;

#pragma unroll
        for (int kk = 0; kk < 32; kk += 8) {
            unsigned af[2][4];
#pragma unroll
            for (int mt = 0; mt < 2; mt++) {
                const float* ar = As + (wm + mt * 16 + g) * GLD + kk + q;
                af[mt][0] = __float_as_uint(ar[0]);
                af[mt][1] = __float_as_uint(ar[8 * GLD]);
                af[mt][2] = __float_as_uint(ar[4]);
                af[mt][3] = __float_as_uint(ar[8 * GLD + 4]);
            }
#pragma unroll
            for (int nt = 0; nt < 8; nt++) {
                const float* br = Bs + (wn + nt * 8 + g) * GLD + kk + q;
                unsigned b0 = f2tf(br[0]);   // W raw -> tf32 inline
                unsigned b1 = f2tf(br[4]);
                mma8(acc[0][nt], af[0], b0, b1);
                mma8(acc[1][nt], af[1], b0, b1);
            }
        }

        __syncthreads();
        if (it + 2 < NITER) {
            float* As2 = sh + (it & 1) * 2 * GSTAGE;
            float* Bs2 = As2 + GSTAGE;
            int k0 = (it + 2) * 32;
#pragma unroll
            for (int i = 0; i < 4; i++) {
                int cc = lc + i * 4;
                cp16(As2 + lr * GLD + cc, Ag + (size_t)(m0 + lr) * EE + k0 + cc);
                cp16(Bs2 + lr * GLD + cc, W  + (size_t)(n0 + lr) * EE + k0 + cc);
            }
        }
        asm volatile("cp.async.commit_group;");
    }

    // epilogue: direct register writes
#pragma unroll
    for (int mt = 0; mt < 2; mt++) {
#pragma unroll
        for (int nt = 0; nt < 8; nt++) {
            int r = m0 + wm + mt * 16 + g;
            int c = n0 + wn + nt * 8 + 2 * q;
            float bx = bias[c], by = bias[c + 1];
            float v0 = acc[mt][nt][0] + bx, v1 = acc[mt][nt][1] + by;
            float v2 = acc[mt][nt][2] + bx, v3 = acc[mt][nt][3] + by;
            if (MODE == 0) {
                int b = r >> 11, s = r & (SS - 1);
                int h = c >> 6, d = c & 63;
                float* dst = g_Q;  // placate compiler; real select below
                dst = (Y == g_Q) ? g_Q : (Y == g_K) ? g_K : g_V;
                dst += (((size_t)(b * HH + h)) * SS + s) * DD + d;
                float2 u0; u0.x = __uint_as_float(f2tf(v0)); u0.y = __uint_as_float(f2tf(v1));
                float2 u1; u1.x = __uint_as_float(f2tf(v2)); u1.y = __uint_as_float(f2tf(v3));
                *(float2*)dst = u0;
                *(float2*)(dst + 8 * DD) = u1;   // row r+8 (s+8)
            } else {
                float* dst = Y + (size_t)r * EE + c;
                float2 u0; u0.x = v0; u0.y = v1;
                float2 u1; u1.x = v2; u1.y = v3;
                *(float2*)dst = u0;
                *(float2*)(dst + 8 * EE) = u1;
            }
        }
    }
}

// ---------------------------------------------------------------------------
// Flash attention, FA2-style register-resident, mma.sync m16n8k8 tf32.
// Writes tf32-rounded O into g_O for the O projection.
// ---------------------------------------------------------------------------
#define LDS_ 68
#define TILE_F (64 * LDS_)
#define QSTAGE_F (128 * LDS_)

__global__ void __launch_bounds__(256, 1) attn_kernel()
{
    extern __shared__ float sh[];
    float* Qs = sh;
    float* Kbuf0 = sh + QSTAGE_F;
    float* Vbuf0 = Kbuf0 + TILE_F;
    float* Kbuf1 = Vbuf0 + TILE_F;
    float* Vbuf1 = Kbuf1 + TILE_F;

    const int tid  = threadIdx.x;
    const int warp = tid >> 5;
    const int lane = tid & 31;
    const int g    = lane >> 2;
    const int q    = lane & 3;
    const int bh   = blockIdx.y;
    const int q0   = blockIdx.x * 128;

    const float* Qg = g_Q + (size_t)bh * SS * DD;
    const float* Kg = g_K + (size_t)bh * SS * DD;
    const float* Vg = g_V + (size_t)bh * SS * DD;

#pragma unroll
    for (int t = 0; t < 2; t++) {
        float* Kd = t ? Kbuf1 : Kbuf0;
        float* Vd = t ? Vbuf1 : Vbuf0;
#pragma unroll
        for (int i = 0; i < 4; i++) {
            int idx = tid + i * 256;
            int r = idx >> 4, c = (idx & 15) * 4;
            cp16(Kd + r * LDS_ + c, Kg + (size_t)(t * 64 + r) * 64 + c);
            cp16(Vd + r * LDS_ + c, Vg + (size_t)(t * 64 + r) * 64 + c);
        }
        asm volatile("cp.async.commit_group;");
    }

#pragma unroll
    for (int i = 0; i < 8; i++) {
        int idx = tid + i * 256;
        int r = idx >> 4, c = (idx & 15) * 4;
        *(float4*)(Qs + r * LDS_ + c) = *(const float4*)(Qg + (size_t)(q0 + r) * 64 + c);
    }
    __syncthreads();

    const float qscale = 0.125f * 1.44269504088896340736f;  // D^-0.5 * log2(e)
    const int rbase = warp * 16;
    unsigned qf[8][4];
#pragma unroll
    for (int ks = 0; ks < 8; ks++) {
        qf[ks][0] = f2tf(Qs[(rbase + g)     * LDS_ + 8 * ks + q]     * qscale);
        qf[ks][1] = f2tf(Qs[(rbase + g + 8) * LDS_ + 8 * ks + q]     * qscale);
        qf[ks][2] = f2tf(Qs[(rbase + g)     * LDS_ + 8 * ks + q + 4] * qscale);
        qf[ks][3] = f2tf(Qs[(rbase + g + 8) * LDS_ + 8 * ks + q + 4] * qscale);
    }

    float o[8][4];
#pragma unroll
    for (int i = 0; i < 8; i++)
#pragma unroll
        for (int k = 0; k < 4; k++) o[i][k] = 0.0f;
    float m0 = -INFINITY, m1 = -INFINITY, l0 = 0.0f, l1 = 0.0f;

    const int src1 = (lane & ~3) | (q >> 1);
    const int src2 = src1 + 2;
    const bool odd = q & 1;

    for (int j = 0; j < SS / 64; j++) {
        asm volatile("cp.async.wait_group 1;");
        __syncthreads();
        const float* K = (j & 1) ? Kbuf1 : Kbuf0;
        const float* V = (j & 1) ? Vbuf1 : Vbuf0;

        float s[8][4];
#pragma unroll
        for (int nt = 0; nt < 8; nt++) {
            s[nt][0] = s[nt][1] = s[nt][2] = s[nt][3] = 0.0f;
#pragma unroll
            for (int ks = 0; ks < 8; ks++) {
                unsigned b0 = __float_as_uint(K[(8 * nt + g) * LDS_ + 8 * ks + q]);
                unsigned b1 = __float_as_uint(K[(8 * nt + g) * LDS_ + 8 * ks + q + 4]);
                mma8(s[nt], qf[ks], b0, b1);
            }
        }

        float mx0 = -INFINITY, mx1 = -INFINITY;
#pragma unroll
        for (int nt = 0; nt < 8; nt++) {
            mx0 = fmaxf(mx0, fmaxf(s[nt][0], s[nt][1]));
            mx1 = fmaxf(mx1, fmaxf(s[nt][2], s[nt][3]));
        }
        mx0 = fmaxf(mx0, __shfl_xor_sync(0xffffffffu, mx0, 1));
        mx0 = fmaxf(mx0, __shfl_xor_sync(0xffffffffu, mx0, 2));
        mx1 = fmaxf(mx1, __shfl_xor_sync(0xffffffffu, mx1, 1));
        mx1 = fmaxf(mx1, __shfl_xor_sync(0xffffffffu, mx1, 2));
        float mn0 = fmaxf(m0, mx0), mn1 = fmaxf(m1, mx1);
        float cr0 = ex2f(m0 - mn0), cr1 = ex2f(m1 - mn1);
        float rs0 = 0.0f, rs1 = 0.0f;
#pragma unroll
        for (int nt = 0; nt < 8; nt++) {
            s[nt][0] = ex2f(s[nt][0] - mn0);
            s[nt][1] = ex2f(s[nt][1] - mn0);
            s[nt][2] = ex2f(s[nt][2] - mn1);
            s[nt][3] = ex2f(s[nt][3] - mn1);
            rs0 += s[nt][0] + s[nt][1];
            rs1 += s[nt][2] + s[nt][3];
        }
        rs0 += __shfl_xor_sync(0xffffffffu, rs0, 1);
        rs0 += __shfl_xor_sync(0xffffffffu, rs0, 2);
        rs1 += __shfl_xor_sync(0xffffffffu, rs1, 1);
        rs1 += __shfl_xor_sync(0xffffffffu, rs1, 2);
        l0 = l0 * cr0 + rs0;
        l1 = l1 * cr1 + rs1;
#pragma unroll
        for (int nt = 0; nt < 8; nt++) {
            o[nt][0] *= cr0; o[nt][1] *= cr0;
            o[nt][2] *= cr1; o[nt][3] *= cr1;
        }
        m0 = mn0; m1 = mn1;

        unsigned pf[8][4];
#pragma unroll
        for (int nt = 0; nt < 8; nt++) {
            float v00 = __shfl_sync(0xffffffffu, s[nt][0], src1);
            float v01 = __shfl_sync(0xffffffffu, s[nt][1], src1);
            float v10 = __shfl_sync(0xffffffffu, s[nt][2], src1);
            float v11 = __shfl_sync(0xffffffffu, s[nt][3], src1);
            float w00 = __shfl_sync(0xffffffffu, s[nt][0], src2);
            float w01 = __shfl_sync(0xffffffffu, s[nt][1], src2);
            float w10 = __shfl_sync(0xffffffffu, s[nt][2], src2);
            float w11 = __shfl_sync(0xffffffffu, s[nt][3], src2);
            pf[nt][0] = f2tf(odd ? v01 : v00);
            pf[nt][1] = f2tf(odd ? v11 : v10);
            pf[nt][2] = f2tf(odd ? w01 : w00);
            pf[nt][3] = f2tf(odd ? w11 : w10);
        }

#pragma unroll
        for (int nt2 = 0; nt2 < 8; nt2++) {
#pragma unroll
            for (int t = 0; t < 8; t++) {
                unsigned b0 = __float_as_uint(V[(8 * t + q)     * LDS_ + 8 * nt2 + g]);
                unsigned b1 = __float_as_uint(V[(8 * t + q + 4) * LDS_ + 8 * nt2 + g]);
                mma8(o[nt2], pf[t], b0, b1);
            }
        }

        __syncthreads();
        if (j + 2 < SS / 64) {
            float* Kd = (j & 1) ? Kbuf1 : Kbuf0;
            float* Vd = (j & 1) ? Vbuf1 : Vbuf0;
#pragma unroll
            for (int i = 0; i < 4; i++) {
                int idx = tid + i * 256;
                int r = idx >> 4, c = (idx & 15) * 4;
                cp16(Kd + r * LDS_ + c, Kg + (size_t)((j + 2) * 64 + r) * 64 + c);
                cp16(Vd + r * LDS_ + c, Vg + (size_t)((j + 2) * 64 + r) * 64 + c);
            }
        }
        asm volatile("cp.async.commit_group;");
    }

    float inv0 = 1.0f / l0, inv1 = 1.0f / l1;
    int b = bh / HH, h = bh % HH;
    size_t row0 = (size_t)b * SS + q0 + rbase + g;
    float* d0 = g_O + row0 * EE + h * DD;
    float* d1 = d0 + 8 * EE;
#pragma unroll
    for (int nt2 = 0; nt2 < 8; nt2++) {
        float2 u;
        u.x = __uint_as_float(f2tf(o[nt2][0] * inv0));
        u.y = __uint_as_float(f2tf(o[nt2][1] * inv0));
        *(float2*)(d0 + 8 * nt2 + 2 * q) = u;
        float2 w;
        w.x = __uint_as_float(f2tf(o[nt2][2] * inv1));
        w.y = __uint_as_float(f2tf(o[nt2][3] * inv1));
        *(float2*)(d1 + 8 * nt2 + 2 * q) = w;
    }
}

// ---------------------------------------------------------------------------
extern "C" void kernel_launch(void* const* d_in, const int* in_sizes, int n_in,
                              void* d_out, int out_size)
{
    const float* x  = (const float*)d_in[0];
    const float* Wq = (const float*)d_in[1];
    const float* bq = (const float*)d_in[2];
    const float* Wk = (const float*)d_in[3];
    const float* bk = (const float*)d_in[4];
    const float* Wv = (const float*)d_in[5];
    const float* bv = (const float*)d_in[6];
    const float* Wo = (const float*)d_in[7];
    const float* bo = (const float*)d_in[8];
    float* out = (float*)d_out;

    (void)in_sizes; (void)n_in; (void)out_size;

    const int gemm_smem = 4 * GSTAGE * sizeof(float);  // 73728
    cudaFuncSetAttribute(gemm_tc<0>, cudaFuncAttributeMaxDynamicSharedMemorySize, gemm_smem);
    cudaFuncSetAttribute(gemm_tc<1>, cudaFuncAttributeMaxDynamicSharedMemorySize, gemm_smem);
    const int attn_smem = (QSTAGE_F + 4 * TILE_F) * sizeof(float);
    cudaFuncSetAttribute(attn_kernel, cudaFuncAttributeMaxDynamicSharedMemorySize, attn_smem);

    // x -> tf32-rounded into g_O (dead until attention writes it)
    round_x_kernel<<<MM * EE / 4 / 256, 256>>>((const float4*)x);

    dim3 gq(MM / 128, EE / 128, 3);
    gemm_tc<0><<<gq, 256, gemm_smem>>>(Wq, bq, Wk, bk, Wv, bv, nullptr);

    attn_kernel<<<dim3(SS / 128, BB * HH), 256, attn_smem>>>();

    dim3 go(MM / 128, EE / 128, 1);
    gemm_tc<1><<<go, 256, gemm_smem>>>(Wo, bo, nullptr, nullptr, nullptr, nullptr, out);
}

// round 5
// speedup vs baseline: 3.4465x; 1.1433x over previous
#include <cuda_runtime.h>
#include <math.h>

#define BB 2
#define SS 2048
#define EE 1024
#define HH 16
#define DD 64
#define MM (BB * SS)   // 4096

// Scratch: exactly 64 MiB of __device__ globals (proven footprint).
// g_O triple-duty: rounded X for QKV proj -> attention output for O proj.
// g_V stored TRANSPOSED per head: [B,H,D,S] so attention V fragments ldmatrix.
__device__ float g_Q[MM * EE];          // [B,H,S,D] tf32-rounded
__device__ float g_K[MM * EE];          // [B,H,S,D] tf32-rounded
__device__ float g_V[MM * EE];          // [B,H,D,S] tf32-rounded (transposed)
__device__ float g_O[MM * EE];          // [M,E] tf32-rounded (X, then attn O)

// ---------------------------------------------------------------------------
// helpers
// ---------------------------------------------------------------------------
__device__ __forceinline__ unsigned f2tf(float f) {
    unsigned u;
    asm("cvt.rna.tf32.f32 %0, %1;" : "=r"(u) : "f"(f));
    return u;
}
__device__ __forceinline__ float ex2f(float x) {
    float y;
    asm("ex2.approx.f32 %0, %1;" : "=f"(y) : "f"(x));
    return y;
}
__device__ __forceinline__ void mma8(float* c, const unsigned* a, unsigned b0, unsigned b1) {
    asm volatile(
        "mma.sync.aligned.m16n8k8.row.col.f32.tf32.tf32.f32 "
        "{%0,%1,%2,%3}, {%4,%5,%6,%7}, {%8,%9}, {%0,%1,%2,%3};"
        : "+f"(c[0]), "+f"(c[1]), "+f"(c[2]), "+f"(c[3])
        : "r"(a[0]), "r"(a[1]), "r"(a[2]), "r"(a[3]), "r"(b0), "r"(b1));
}
__device__ __forceinline__ void cp16(float* smem, const float* gmem) {
    unsigned s = (unsigned)__cvta_generic_to_shared(smem);
    asm volatile("cp.async.cg.shared.global [%0], [%1], 16;" :: "r"(s), "l"(gmem));
}
// ldmatrix x4 on f32 data viewed as b16 pairs: lane l of matrix i receives
// f32 element (row = l/4, col = l%4) -> exactly the tf32 mma fragment layout.
__device__ __forceinline__ void ldsm4(unsigned* r, const float* p) {
    unsigned a = (unsigned)__cvta_generic_to_shared(p);
    asm volatile("ldmatrix.sync.aligned.m8n8.x4.shared.b16 {%0,%1,%2,%3}, [%4];"
                 : "=r"(r[0]), "=r"(r[1]), "=r"(r[2]), "=r"(r[3]) : "r"(a));
}

// ---------------------------------------------------------------------------
// round x -> tf32, written straight into g_O
// ---------------------------------------------------------------------------
__global__ void __launch_bounds__(256) round_x_kernel(const float4* __restrict__ src)
{
    int i = blockIdx.x * 256 + threadIdx.x;
    float4 v = src[i];
    v.x = __uint_as_float(f2tf(v.x));
    v.y = __uint_as_float(f2tf(v.y));
    v.z = __uint_as_float(f2tf(v.z));
    v.w = __uint_as_float(f2tf(v.w));
    ((float4*)g_O)[i] = v;
}

// ---------------------------------------------------------------------------
// Tensor-core NT GEMM: C[M,N] = A[M,K] @ W[N,K]^T + bias
// A from g_O (pre-rounded tf32, raw ldmatrix). W raw fp32, ldmatrix + reg cvt.
// 128x128x32 tiles, 256 threads, cp.async double buffered.
// MODE 0: z selects W/bias; z=0,1 -> Q/K [B,H,S,D]; z=2 -> V transposed [B,H,D,S].
// MODE 1: plain [M,E] fp32 output to Yout.
// ---------------------------------------------------------------------------
#define GLD 36                       // padded smem row stride (floats)
#define GSTAGE (128 * GLD)           // floats per operand stage

template <int MODE>
__global__ void __launch_bounds__(256)
gemm_tc(const float* __restrict__ W0, const float* __restrict__ b0v,
        const float* __restrict__ W1, const float* __restrict__ b1v,
        const float* __restrict__ W2, const float* __restrict__ b2v,
        float* __restrict__ Yout)
{
    extern __shared__ float sh[];

    const float* Ag = g_O;
    const float* W;
    const float* bias;
    int z = 0;
    if (MODE == 0) {
        z    = blockIdx.z;
        W    = (z == 0) ? W0 : (z == 1) ? W1 : W2;
        bias = (z == 0) ? b0v : (z == 1) ? b1v : b2v;
    } else {
        W    = W0;
        bias = b0v;
    }

    const int tid  = threadIdx.x;
    const int warp = tid >> 5;
    const int lane = tid & 31;
    const int g    = lane >> 2;
    const int q    = lane & 3;
    const int m0   = blockIdx.x * 128;
    const int n0   = blockIdx.y * 128;
    const int wm   = (warp >> 1) * 32;   // 4 warp-rows of 32
    const int wn   = (warp & 1) * 64;    // 2 warp-cols of 64

    const int lr = tid >> 1;             // load row 0..127
    const int lc = (tid & 1) * 16;       // load col base 0/16

    // ldmatrix per-lane address components
    const int a_row = (lane & 15);            // + wm + mt*16
    const int a_col = (lane & 16) >> 2;       // + kk
    const int b_row = (lane & 7) + ((lane & 16) >> 1);  // + wn + p*16
    const int b_col = (lane & 8) >> 1;        // + kk

    float acc[2][8][4];
#pragma unroll
    for (int mt = 0; mt < 2; mt++)
#pragma unroll
        for (int nt = 0; nt < 8; nt++)
#pragma unroll
            for (int t = 0; t < 4; t++) acc[mt][nt][t] = 0.0f;

    // prefetch stages 0,1
#pragma unroll
    for (int st = 0; st < 2; st++) {
        float* As = sh + st * 2 * GSTAGE;
        float* Bs = As + GSTAGE;
        int k0 = st * 32;
#pragma unroll
        for (int i = 0; i < 4; i++) {
            int cc = lc + i * 4;
            cp16(As + lr * GLD + cc, Ag + (size_t)(m0 + lr) * EE + k0 + cc);
            cp16(Bs + lr * GLD + cc, W  + (size_t)(n0 + lr) * EE + k0 + cc);
        }
        asm volatile("cp.async.commit_group;");
    }

    const int NITER = EE / 32;
    for (int it = 0; it < NITER; it++) {
        asm volatile("cp.async.wait_group 1;");
        __syncthreads();
        const float* As = sh + (it & 1) * 2 * GSTAGE;
        const float* Bs = As + GSTAGE;

#pragma unroll
        for (int kk = 0; kk < 32; kk += 8) {
            unsigned af[2][4];
            ldsm4(af[0], As + (wm +      a_row) * GLD + kk + a_col);
            ldsm4(af[1], As + (wm + 16 + a_row) * GLD + kk + a_col);
#pragma unroll
            for (int p = 0; p < 4; p++) {
                unsigned bq[4];
                ldsm4(bq, Bs + (wn + p * 16 + b_row) * GLD + kk + b_col);
                unsigned c0 = f2tf(__uint_as_float(bq[0]));
                unsigned c1 = f2tf(__uint_as_float(bq[1]));
                unsigned c2 = f2tf(__uint_as_float(bq[2]));
                unsigned c3 = f2tf(__uint_as_float(bq[3]));
                mma8(acc[0][2 * p],     af[0], c0, c1);
                mma8(acc[1][2 * p],     af[1], c0, c1);
                mma8(acc[0][2 * p + 1], af[0], c2, c3);
                mma8(acc[1][2 * p + 1], af[1], c2, c3);
            }
        }

        __syncthreads();
        if (it + 2 < NITER) {
            float* As2 = sh + (it & 1) * 2 * GSTAGE;
            float* Bs2 = As2 + GSTAGE;
            int k0 = (it + 2) * 32;
#pragma unroll
            for (int i = 0; i < 4; i++) {
                int cc = lc + i * 4;
                cp16(As2 + lr * GLD + cc, Ag + (size_t)(m0 + lr) * EE + k0 + cc);
                cp16(Bs2 + lr * GLD + cc, W  + (size_t)(n0 + lr) * EE + k0 + cc);
            }
        }
        asm volatile("cp.async.commit_group;");
    }

    // epilogue: direct register writes
#pragma unroll
    for (int mt = 0; mt < 2; mt++) {
#pragma unroll
        for (int nt = 0; nt < 8; nt++) {
            int r = m0 + wm + mt * 16 + g;
            int c = n0 + wn + nt * 8 + 2 * q;
            float bx = bias[c], by = bias[c + 1];
            float v0 = acc[mt][nt][0] + bx, v1 = acc[mt][nt][1] + by;
            float v2 = acc[mt][nt][2] + bx, v3 = acc[mt][nt][3] + by;
            if (MODE == 0) {
                int b = r >> 11, s = r & (SS - 1);
                int h = c >> 6, d = c & 63;
                if (z == 2) {
                    // V transposed: [B,H,D,S]
                    float* dst = g_V + (((size_t)(b * HH + h)) * DD + d) * SS + s;
                    dst[0]      = __uint_as_float(f2tf(v0));   // (d,   s)
                    dst[SS]     = __uint_as_float(f2tf(v1));   // (d+1, s)
                    dst[8]      = __uint_as_float(f2tf(v2));   // (d,   s+8)
                    dst[SS + 8] = __uint_as_float(f2tf(v3));   // (d+1, s+8)
                } else {
                    float* dst = (z == 0) ? g_Q : g_K;
                    dst += (((size_t)(b * HH + h)) * SS + s) * DD + d;
                    float2 u0; u0.x = __uint_as_float(f2tf(v0)); u0.y = __uint_as_float(f2tf(v1));
                    float2 u1; u1.x = __uint_as_float(f2tf(v2)); u1.y = __uint_as_float(f2tf(v3));
                    *(float2*)dst = u0;
                    *(float2*)(dst + 8 * DD) = u1;   // row s+8
                }
            } else {
                float* dst = Yout + (size_t)r * EE + c;
                float2 u0; u0.x = v0; u0.y = v1;
                float2 u1; u1.x = v2; u1.y = v3;
                *(float2*)dst = u0;
                *(float2*)(dst + 8 * EE) = u1;
            }
        }
    }
}

// ---------------------------------------------------------------------------
// Flash attention, register-resident, mma.sync m16n8k8 tf32, ldmatrix
// fragments for K and (transposed) V. Writes tf32-rounded O into g_O.
// ---------------------------------------------------------------------------
#define LDS_ 68
#define TILE_F (64 * LDS_)
#define QSTAGE_F (128 * LDS_)

__global__ void __launch_bounds__(256, 1) attn_kernel()
{
    extern __shared__ float sh[];
    float* Qs = sh;
    float* Kbuf0 = sh + QSTAGE_F;
    float* Vbuf0 = Kbuf0 + TILE_F;
    float* Kbuf1 = Vbuf0 + TILE_F;
    float* Vbuf1 = Kbuf1 + TILE_F;

    const int tid  = threadIdx.x;
    const int warp = tid >> 5;
    const int lane = tid & 31;
    const int g    = lane >> 2;
    const int q    = lane & 3;
    const int bh   = blockIdx.y;
    const int q0   = blockIdx.x * 128;

    const float* Qg = g_Q + (size_t)bh * SS * DD;
    const float* Kg = g_K + (size_t)bh * SS * DD;
    const float* Vg = g_V + (size_t)bh * SS * DD;   // transposed [D][S]

    // ldmatrix per-lane address components (B-fragment pattern)
    const int b_row = (lane & 7) + ((lane & 16) >> 1);  // + p*16
    const int b_col = (lane & 8) >> 1;

#pragma unroll
    for (int t = 0; t < 2; t++) {
        float* Kd = t ? Kbuf1 : Kbuf0;
        float* Vd = t ? Vbuf1 : Vbuf0;
#pragma unroll
        for (int i = 0; i < 4; i++) {
            int idx = tid + i * 256;
            int r = idx >> 4, c = (idx & 15) * 4;
            cp16(Kd + r * LDS_ + c, Kg + (size_t)(t * 64 + r) * 64 + c);
            cp16(Vd + r * LDS_ + c, Vg + (size_t)r * SS + t * 64 + c);  // rows=d
        }
        asm volatile("cp.async.commit_group;");
    }

#pragma unroll
    for (int i = 0; i < 8; i++) {
        int idx = tid + i * 256;
        int r = idx >> 4, c = (idx & 15) * 4;
        *(float4*)(Qs + r * LDS_ + c) = *(const float4*)(Qg + (size_t)(q0 + r) * 64 + c);
    }
    __syncthreads();

    const float qscale = 0.125f * 1.44269504088896340736f;  // D^-0.5 * log2(e)
    const int rbase = warp * 16;
    unsigned qf[8][4];
#pragma unroll
    for (int ks = 0; ks < 8; ks++) {
        qf[ks][0] = f2tf(Qs[(rbase + g)     * LDS_ + 8 * ks + q]     * qscale);
        qf[ks][1] = f2tf(Qs[(rbase + g + 8) * LDS_ + 8 * ks + q]     * qscale);
        qf[ks][2] = f2tf(Qs[(rbase + g)     * LDS_ + 8 * ks + q + 4] * qscale);
        qf[ks][3] = f2tf(Qs[(rbase + g + 8) * LDS_ + 8 * ks + q + 4] * qscale);
    }

    float o[8][4];
#pragma unroll
    for (int i = 0; i < 8; i++)
#pragma unroll
        for (int k = 0; k < 4; k++) o[i][k] = 0.0f;
    float m0 = -INFINITY, m1 = -INFINITY, l0 = 0.0f, l1 = 0.0f;

    const int src1 = (lane & ~3) | (q >> 1);
    const int src2 = src1 + 2;
    const bool odd = q & 1;

    for (int j = 0; j < SS / 64; j++) {
        asm volatile("cp.async.wait_group 1;");
        __syncthreads();
        const float* K = (j & 1) ? Kbuf1 : Kbuf0;
        const float* V = (j & 1) ? Vbuf1 : Vbuf0;

        // ---- S = (Q*scale) K^T : ldmatrix K fragments ----
        float s[8][4];
#pragma unroll
        for (int nt = 0; nt < 8; nt++)
            s[nt][0] = s[nt][1] = s[nt][2] = s[nt][3] = 0.0f;
#pragma unroll
        for (int ks = 0; ks < 8; ks++) {
#pragma unroll
            for (int p = 0; p < 4; p++) {
                unsigned kb[4];
                ldsm4(kb, K + (p * 16 + b_row) * LDS_ + 8 * ks + b_col);
                mma8(s[2 * p],     qf[ks], kb[0], kb[1]);
                mma8(s[2 * p + 1], qf[ks], kb[2], kb[3]);
            }
        }

        // ---- online softmax ----
        float mx0 = -INFINITY, mx1 = -INFINITY;
#pragma unroll
        for (int nt = 0; nt < 8; nt++) {
            mx0 = fmaxf(mx0, fmaxf(s[nt][0], s[nt][1]));
            mx1 = fmaxf(mx1, fmaxf(s[nt][2], s[nt][3]));
        }
        mx0 = fmaxf(mx0, __shfl_xor_sync(0xffffffffu, mx0, 1));
        mx0 = fmaxf(mx0, __shfl_xor_sync(0xffffffffu, mx0, 2));
        mx1 = fmaxf(mx1, __shfl_xor_sync(0xffffffffu, mx1, 1));
        mx1 = fmaxf(mx1, __shfl_xor_sync(0xffffffffu, mx1, 2));
        float mn0 = fmaxf(m0, mx0), mn1 = fmaxf(m1, mx1);
        float cr0 = ex2f(m0 - mn0), cr1 = ex2f(m1 - mn1);
        float rs0 = 0.0f, rs1 = 0.0f;
#pragma unroll
        for (int nt = 0; nt < 8; nt++) {
            s[nt][0] = ex2f(s[nt][0] - mn0);
            s[nt][1] = ex2f(s[nt][1] - mn0);
            s[nt][2] = ex2f(s[nt][2] - mn1);
            s[nt][3] = ex2f(s[nt][3] - mn1);
            rs0 += s[nt][0] + s[nt][1];
            rs1 += s[nt][2] + s[nt][3];
        }
        rs0 += __shfl_xor_sync(0xffffffffu, rs0, 1);
        rs0 += __shfl_xor_sync(0xffffffffu, rs0, 2);
        rs1 += __shfl_xor_sync(0xffffffffu, rs1, 1);
        rs1 += __shfl_xor_sync(0xffffffffu, rs1, 2);
        l0 = l0 * cr0 + rs0;
        l1 = l1 * cr1 + rs1;
#pragma unroll
        for (int nt = 0; nt < 8; nt++) {
            o[nt][0] *= cr0; o[nt][1] *= cr0;
            o[nt][2] *= cr1; o[nt][3] *= cr1;
        }
        m0 = mn0; m1 = mn1;

        // ---- permute P (C layout) -> A fragments via quad shuffles ----
        unsigned pf[8][4];
#pragma unroll
        for (int nt = 0; nt < 8; nt++) {
            float v00 = __shfl_sync(0xffffffffu, s[nt][0], src1);
            float v01 = __shfl_sync(0xffffffffu, s[nt][1], src1);
            float v10 = __shfl_sync(0xffffffffu, s[nt][2], src1);
            float v11 = __shfl_sync(0xffffffffu, s[nt][3], src1);
            float w00 = __shfl_sync(0xffffffffu, s[nt][0], src2);
            float w01 = __shfl_sync(0xffffffffu, s[nt][1], src2);
            float w10 = __shfl_sync(0xffffffffu, s[nt][2], src2);
            float w11 = __shfl_sync(0xffffffffu, s[nt][3], src2);
            pf[nt][0] = f2tf(odd ? v01 : v00);
            pf[nt][1] = f2tf(odd ? v11 : v10);
            pf[nt][2] = f2tf(odd ? w01 : w00);
            pf[nt][3] = f2tf(odd ? w11 : w10);
        }

        // ---- O += P V : ldmatrix transposed-V fragments ----
#pragma unroll
        for (int t = 0; t < 8; t++) {
#pragma unroll
            for (int p = 0; p < 4; p++) {
                unsigned vb[4];
                ldsm4(vb, V + (p * 16 + b_row) * LDS_ + 8 * t + b_col);
                mma8(o[2 * p],     pf[t], vb[0], vb[1]);
                mma8(o[2 * p + 1], pf[t], vb[2], vb[3]);
            }
        }

        __syncthreads();
        if (j + 2 < SS / 64) {
            float* Kd = (j & 1) ? Kbuf1 : Kbuf0;
            float* Vd = (j & 1) ? Vbuf1 : Vbuf0;
#pragma unroll
            for (int i = 0; i < 4; i++) {
                int idx = tid + i * 256;
                int r = idx >> 4, c = (idx & 15) * 4;
                cp16(Kd + r * LDS_ + c, Kg + (size_t)((j + 2) * 64 + r) * 64 + c);
                cp16(Vd + r * LDS_ + c, Vg + (size_t)r * SS + (j + 2) * 64 + c);
            }
        }
        asm volatile("cp.async.commit_group;");
    }

    float inv0 = 1.0f / l0, inv1 = 1.0f / l1;
    int b = bh / HH, h = bh % HH;
    size_t row0 = (size_t)b * SS + q0 + rbase + g;
    float* d0 = g_O + row0 * EE + h * DD;
    float* d1 = d0 + 8 * EE;
#pragma unroll
    for (int nt2 = 0; nt2 < 8; nt2++) {
        float2 u;
        u.x = __uint_as_float(f2tf(o[nt2][0] * inv0));
        u.y = __uint_as_float(f2tf(o[nt2][1] * inv0));
        *(float2*)(d0 + 8 * nt2 + 2 * q) = u;
        float2 w;
        w.x = __uint_as_float(f2tf(o[nt2][2] * inv1));
        w.y = __uint_as_float(f2tf(o[nt2][3] * inv1));
        *(float2*)(d1 + 8 * nt2 + 2 * q) = w;
    }
}

// ---------------------------------------------------------------------------
extern "C" void kernel_launch(void* const* d_in, const int* in_sizes, int n_in,
                              void* d_out, int out_size)
{
    const float* x  = (const float*)d_in[0];
    const float* Wq = (const float*)d_in[1];
    const float* bq = (const float*)d_in[2];
    const float* Wk = (const float*)d_in[3];
    const float* bk = (const float*)d_in[4];
    const float* Wv = (const float*)d_in[5];
    const float* bv = (const float*)d_in[6];
    const float* Wo = (const float*)d_in[7];
    const float* bo = (const float*)d_in[8];
    float* out = (float*)d_out;

    (void)in_sizes; (void)n_in; (void)out_size;

    const int gemm_smem = 4 * GSTAGE * sizeof(float);  // 73728
    cudaFuncSetAttribute(gemm_tc<0>, cudaFuncAttributeMaxDynamicSharedMemorySize, gemm_smem);
    cudaFuncSetAttribute(gemm_tc<1>, cudaFuncAttributeMaxDynamicSharedMemorySize, gemm_smem);
    const int attn_smem = (QSTAGE_F + 4 * TILE_F) * sizeof(float);
    cudaFuncSetAttribute(attn_kernel, cudaFuncAttributeMaxDynamicSharedMemorySize, attn_smem);

    // x -> tf32-rounded into g_O (dead until attention writes it)
    round_x_kernel<<<MM * EE / 4 / 256, 256>>>((const float4*)x);

    dim3 gq(MM / 128, EE / 128, 3);
    gemm_tc<0><<<gq, 256, gemm_smem>>>(Wq, bq, Wk, bk, Wv, bv, nullptr);

    attn_kernel<<<dim3(SS / 128, BB * HH), 256, attn_smem>>>();

    dim3 go(MM / 128, EE / 128, 1);
    gemm_tc<1><<<go, 256, gemm_smem>>>(Wo, bo, nullptr, nullptr, nullptr, nullptr, out);
}